// round 9
// baseline (speedup 1.0000x reference)
#include <cuda_runtime.h>

static constexpr int B = 16, C = 21, H = 512, W = 512;
static constexpr int HW = H * W;            // 262144
static constexpr int NPLANES = B * C;       // 336
static constexpr int P4 = HW / 4;           // 65536 float4 per plane
static constexpr int TPB = 256;
static constexpr int BPP = 16;              // blocks per plane (was 64)
static constexpr int ITERS = P4 / (TPB * BPP); // 16
static constexpr int OUTER = 4, INNER = ITERS / OUTER; // 4 x 4

// Per-block partials (every slot written every call -> no init needed).
__device__ float g_pta[NPLANES * BPP];
__device__ float g_ptb[NPLANES * BPP];
__device__ float g_pit[NPLANES * BPP];
// Per-plane results.
__device__ float g_dice[NPLANES];
__device__ float g_valid[NPLANES];
// Counters: zero at module load; reset to 0 before kernel ends -> graph-safe.
__device__ int g_cnt[NPLANES];
__device__ int g_done;

__global__ __launch_bounds__(TPB) void dice_kernel(
    const float4* __restrict__ yp, const float4* __restrict__ yt,
    const int* __restrict__ bg_ptr, float* __restrict__ out)
{
    const int plane = blockIdx.x / BPP;
    const int seg   = blockIdx.x % BPP;
    const size_t base = (size_t)plane * P4 + (size_t)seg * (TPB * ITERS);

    const float4* p = yp + base + threadIdx.x;
    const float4* t = yt + base + threadIdx.x;

    // ---- streaming phase (DRAM-bound): 16 iters, 8 LDG.128 batched/outer ----
    float ta = 0.0f, tb = 0.0f, it = 0.0f;
    #pragma unroll
    for (int o = 0; o < OUTER; o++) {
        float4 a[INNER], b[INNER];
        #pragma unroll
        for (int k = 0; k < INNER; k++) {
            a[k] = __ldcs(p + (o * INNER + k) * TPB);   // y_pred
            b[k] = __ldcs(t + (o * INNER + k) * TPB);   // y_true
        }
        #pragma unroll
        for (int k = 0; k < INNER; k++) {
            tb += (a[k].x + a[k].y) + (a[k].z + a[k].w);
            ta += (b[k].x + b[k].y) + (b[k].z + b[k].w);
            it += a[k].x * b[k].x + a[k].y * b[k].y
                + a[k].z * b[k].z + a[k].w * b[k].w;
        }
    }

    // ---- block reduce ----
    #pragma unroll
    for (int o = 16; o > 0; o >>= 1) {
        ta += __shfl_down_sync(0xFFFFFFFFu, ta, o);
        tb += __shfl_down_sync(0xFFFFFFFFu, tb, o);
        it += __shfl_down_sync(0xFFFFFFFFu, it, o);
    }

    __shared__ float sta[TPB / 32], stb[TPB / 32], sit[TPB / 32];
    __shared__ int s_last;
    const int wid = threadIdx.x >> 5, lid = threadIdx.x & 31;
    if (lid == 0) { sta[wid] = ta; stb[wid] = tb; sit[wid] = it; }
    __syncthreads();

    if (threadIdx.x == 0) {
        float A = 0.0f, Bv = 0.0f, I = 0.0f;
        #pragma unroll
        for (int i = 0; i < TPB / 32; i++) { A += sta[i]; Bv += stb[i]; I += sit[i]; }
        const int slot = plane * BPP + seg;
        __stcg(&g_pta[slot], A);
        __stcg(&g_ptb[slot], Bv);
        __stcg(&g_pit[slot], I);
        __threadfence();
        int old = atomicAdd(&g_cnt[plane], 1);
        s_last = (old == BPP - 1);
    }
    __syncthreads();
    if (!s_last || threadIdx.x >= 32) return;

    // ---- last block of this plane: reduce BPP=16 partials (lanes 0..15) ----
    {
        float A = 0.0f, Bv = 0.0f, I = 0.0f;
        if (lid < BPP) {
            const int b0 = plane * BPP + lid;
            A  = __ldcg(&g_pta[b0]);
            Bv = __ldcg(&g_ptb[b0]);
            I  = __ldcg(&g_pit[b0]);
        }
        #pragma unroll
        for (int o = 8; o > 0; o >>= 1) {
            A  += __shfl_down_sync(0xFFFFFFFFu, A,  o);
            Bv += __shfl_down_sync(0xFFFFFFFFu, Bv, o);
            I  += __shfl_down_sync(0xFFFFFFFFu, I,  o);
        }
        int fin = 0;
        if (lid == 0) {
            float valid = (A != 0.0f) ? 1.0f : 0.0f;
            __stcg(&g_dice[plane], valid * (2.0f * I / (A + Bv + 1e-11f)));
            __stcg(&g_valid[plane], valid);
            g_cnt[plane] = 0;               // reset for next graph replay
            __threadfence();
            int old2 = atomicAdd(&g_done, 1);
            fin = (old2 == NPLANES - 1);
        }
        fin = __shfl_sync(0xFFFFFFFFu, fin, 0);
        if (!fin) return;
    }

    // ---- very last finisher: batch epilogue (warp 0, lanes 0..B-1) ----
    {
        __threadfence();
        const int bg = *bg_ptr;
        const int b = lid;
        float tmp = 0.0f, bv = 0.0f;
        if (b < B) {
            float cnt = 0.0f, sd = 0.0f;
            for (int c = bg; c < C; c++) {
                cnt += __ldcg(&g_valid[b * C + c]);
                sd  += __ldcg(&g_dice[b * C + c]);
            }
            float denom = cnt - (float)bg;      // cpt2 - bg, as in reference
            if (denom != 0.0f) {
                tmp = sd / denom;
                bv = 1.0f;
            }
        }
        #pragma unroll
        for (int o = 16; o > 0; o >>= 1) {
            tmp += __shfl_down_sync(0xFFFFFFFFu, tmp, o);
            bv  += __shfl_down_sync(0xFFFFFFFFu, bv,  o);
        }
        if (lid == 0) {
            float cpt1 = bv;
            float loss = 1.0f - tmp / fmaxf(cpt1, 1.0f);
            out[0] = (cpt1 > 0.0f) ? loss : -1.0f;
            g_done = 0;                     // reset for next graph replay
        }
    }
}

extern "C" void kernel_launch(void* const* d_in, const int* in_sizes, int n_in,
                              void* d_out, int out_size)
{
    const float4* y_pred = (const float4*)d_in[0];
    const float4* y_true = (const float4*)d_in[1];
    const int*    bg     = (const int*)d_in[2];
    float*        out    = (float*)d_out;

    dice_kernel<<<NPLANES * BPP, TPB>>>(y_pred, y_true, bg, out);
}

// round 10
// speedup vs baseline: 1.0110x; 1.0110x over previous
#include <cuda_runtime.h>

static constexpr int B = 16, C = 21, H = 512, W = 512;
static constexpr int HW = H * W;            // 262144
static constexpr int NPLANES = B * C;       // 336
static constexpr int P4 = HW / 4;           // 65536 float4 per plane
static constexpr int TPB = 256;
static constexpr int BPP = 16;              // blocks per plane (was 64)
static constexpr int ITERS = P4 / (TPB * BPP); // 16
static constexpr int OUTER = 4, INNER = ITERS / OUTER; // 4 x 4

// Per-block partials (every slot written every call -> no init needed).
__device__ float g_pta[NPLANES * BPP];
__device__ float g_ptb[NPLANES * BPP];
__device__ float g_pit[NPLANES * BPP];
// Per-plane results.
__device__ float g_dice[NPLANES];
__device__ float g_valid[NPLANES];
// Counters: zero at module load; reset to 0 before kernel ends -> graph-safe.
__device__ int g_cnt[NPLANES];
__device__ int g_done;

__global__ __launch_bounds__(TPB) void dice_kernel(
    const float4* __restrict__ yp, const float4* __restrict__ yt,
    const int* __restrict__ bg_ptr, float* __restrict__ out)
{
    const int plane = blockIdx.x / BPP;
    const int seg   = blockIdx.x % BPP;
    const size_t base = (size_t)plane * P4 + (size_t)seg * (TPB * ITERS);

    const float4* p = yp + base + threadIdx.x;
    const float4* t = yt + base + threadIdx.x;

    // ---- streaming phase (DRAM-bound): 16 iters, 8 LDG.128 batched/outer ----
    float ta = 0.0f, tb = 0.0f, it = 0.0f;
    #pragma unroll
    for (int o = 0; o < OUTER; o++) {
        float4 a[INNER], b[INNER];
        #pragma unroll
        for (int k = 0; k < INNER; k++) {
            a[k] = __ldcs(p + (o * INNER + k) * TPB);   // y_pred
            b[k] = __ldcs(t + (o * INNER + k) * TPB);   // y_true
        }
        #pragma unroll
        for (int k = 0; k < INNER; k++) {
            tb += (a[k].x + a[k].y) + (a[k].z + a[k].w);
            ta += (b[k].x + b[k].y) + (b[k].z + b[k].w);
            it += a[k].x * b[k].x + a[k].y * b[k].y
                + a[k].z * b[k].z + a[k].w * b[k].w;
        }
    }

    // ---- block reduce ----
    #pragma unroll
    for (int o = 16; o > 0; o >>= 1) {
        ta += __shfl_down_sync(0xFFFFFFFFu, ta, o);
        tb += __shfl_down_sync(0xFFFFFFFFu, tb, o);
        it += __shfl_down_sync(0xFFFFFFFFu, it, o);
    }

    __shared__ float sta[TPB / 32], stb[TPB / 32], sit[TPB / 32];
    __shared__ int s_last;
    const int wid = threadIdx.x >> 5, lid = threadIdx.x & 31;
    if (lid == 0) { sta[wid] = ta; stb[wid] = tb; sit[wid] = it; }
    __syncthreads();

    if (threadIdx.x == 0) {
        float A = 0.0f, Bv = 0.0f, I = 0.0f;
        #pragma unroll
        for (int i = 0; i < TPB / 32; i++) { A += sta[i]; Bv += stb[i]; I += sit[i]; }
        const int slot = plane * BPP + seg;
        __stcg(&g_pta[slot], A);
        __stcg(&g_ptb[slot], Bv);
        __stcg(&g_pit[slot], I);
        __threadfence();
        int old = atomicAdd(&g_cnt[plane], 1);
        s_last = (old == BPP - 1);
    }
    __syncthreads();
    if (!s_last || threadIdx.x >= 32) return;

    // ---- last block of this plane: reduce BPP=16 partials (lanes 0..15) ----
    {
        float A = 0.0f, Bv = 0.0f, I = 0.0f;
        if (lid < BPP) {
            const int b0 = plane * BPP + lid;
            A  = __ldcg(&g_pta[b0]);
            Bv = __ldcg(&g_ptb[b0]);
            I  = __ldcg(&g_pit[b0]);
        }
        #pragma unroll
        for (int o = 8; o > 0; o >>= 1) {
            A  += __shfl_down_sync(0xFFFFFFFFu, A,  o);
            Bv += __shfl_down_sync(0xFFFFFFFFu, Bv, o);
            I  += __shfl_down_sync(0xFFFFFFFFu, I,  o);
        }
        int fin = 0;
        if (lid == 0) {
            float valid = (A != 0.0f) ? 1.0f : 0.0f;
            __stcg(&g_dice[plane], valid * (2.0f * I / (A + Bv + 1e-11f)));
            __stcg(&g_valid[plane], valid);
            g_cnt[plane] = 0;               // reset for next graph replay
            __threadfence();
            int old2 = atomicAdd(&g_done, 1);
            fin = (old2 == NPLANES - 1);
        }
        fin = __shfl_sync(0xFFFFFFFFu, fin, 0);
        if (!fin) return;
    }

    // ---- very last finisher: batch epilogue (warp 0, lanes 0..B-1) ----
    {
        __threadfence();
        const int bg = *bg_ptr;
        const int b = lid;
        float tmp = 0.0f, bv = 0.0f;
        if (b < B) {
            float cnt = 0.0f, sd = 0.0f;
            for (int c = bg; c < C; c++) {
                cnt += __ldcg(&g_valid[b * C + c]);
                sd  += __ldcg(&g_dice[b * C + c]);
            }
            float denom = cnt - (float)bg;      // cpt2 - bg, as in reference
            if (denom != 0.0f) {
                tmp = sd / denom;
                bv = 1.0f;
            }
        }
        #pragma unroll
        for (int o = 16; o > 0; o >>= 1) {
            tmp += __shfl_down_sync(0xFFFFFFFFu, tmp, o);
            bv  += __shfl_down_sync(0xFFFFFFFFu, bv,  o);
        }
        if (lid == 0) {
            float cpt1 = bv;
            float loss = 1.0f - tmp / fmaxf(cpt1, 1.0f);
            out[0] = (cpt1 > 0.0f) ? loss : -1.0f;
            g_done = 0;                     // reset for next graph replay
        }
    }
}

extern "C" void kernel_launch(void* const* d_in, const int* in_sizes, int n_in,
                              void* d_out, int out_size)
{
    const float4* y_pred = (const float4*)d_in[0];
    const float4* y_true = (const float4*)d_in[1];
    const int*    bg     = (const int*)d_in[2];
    float*        out    = (float*)d_out;

    dice_kernel<<<NPLANES * BPP, TPB>>>(y_pred, y_true, bg, out);
}